// round 10
// baseline (speedup 1.0000x reference)
#include <cuda_runtime.h>
#include <cstdint>

#define NB    2
#define NTT   2
#define NLG   256
#define TT    64
#define SS    256
#define NVV   4
#define FF    16
#define KNN   3
#define CUTOFF   1e-3f
#define MASKVAL  1e6f

#define ROWST 264           // dist tile row stride (floats), pad 4 at s=128
#define CAP   12            // pool capacity per (t, chunk)
#define TPST  104           // pool stride per t (= 8*CAP + 8 pad)  -> banks 0/8/16/24

// dynamic SMEM layout (floats unless noted)
#define OFF_DIST  0                       // 32*264 = 8448 floats
#define OFF_PV    (32*ROWST)              // 32*104 = 3328 floats
#define OFF_PS_B  ((OFF_PV + 32*TPST)*4)  // byte offset of ushort pool
#define OFF_NIB_B (OFF_PS_B + 32*TPST*2)  // byte offset of mask nibbles (256 B)
#define OFF_CNT_B (OFF_NIB_B + 256)       // byte offset of counts (256 B)
#define SMEM_BYTES (OFF_CNT_B + 256)

#define BIGV 3.4e38f
#define BIGI 0x3fffffff

__device__ __forceinline__ bool lessvi(float v, int i, float w, int j) {
    return (v < w) || (v == w && i < j);
}

// exact lexicographic (value, index) top-3 insert
__device__ __forceinline__ void top3_insert_vi(float v, int s,
                                               float& d0, float& d1, float& d2,
                                               int& i0, int& i1, int& i2) {
    if (lessvi(v, s, d2, i2)) {
        if (lessvi(v, s, d1, i1)) {
            d2 = d1; i2 = i1;
            if (lessvi(v, s, d0, i0)) { d1 = d0; i1 = i0; d0 = v; i0 = s; }
            else                      { d1 = v;  i1 = s; }
        } else {
            d2 = v; i2 = s;
        }
    }
}

__device__ __forceinline__ int offmap(int s) {  // s -> padded tile offset
    return s + ((s >> 7) << 2);
}

__global__ __launch_bounds__(256, 4) void interp_kernel(
    const float* __restrict__ x,            // (B,NT, NL*S, NV, F)
    const void*  __restrict__ mask_raw,     // (B,NT, NL*S, NV) — dtype detected
    const float* __restrict__ dist,         // (B, NL, T, S)
    float* __restrict__ out)
{
    extern __shared__ float smf[];
    float*          sd    = smf + OFF_DIST;                       // dist tile
    float*          pv    = smf + OFF_PV;                         // pool values
    unsigned short* pssh  = (unsigned short*)((char*)smf + OFF_PS_B);
    unsigned char*  mnib  = (unsigned char*)((char*)smf + OFF_NIB_B);
    unsigned char*  cnts  = (unsigned char*)((char*)smf + OFF_CNT_B);
    __shared__ int s_flags[2];

    const int bid   = blockIdx.x;
    const int tb    = bid & 1;               // half of the 64 targets
    const int group = bid >> 1;
    const int l     = group & 255;
    const int nt    = (group >> 8) & 1;
    const int b     = group >> 9;
    const int tid   = threadIdx.x;

    if (tid == 0) { s_flags[0] = 0; s_flags[1] = 0; }
    __syncthreads();

    // ---- mask dtype detection from first 1024 bytes ----
    {
        const uchar4* mb = (const uchar4*)mask_raw;
        uchar4 q = mb[tid];
        int u8  = (q.y == 1) | (q.z == 1) | (q.w == 1);
        int f32 = (q.x == 0x3F) | (q.y == 0x3F) | (q.z == 0x3F) | (q.w == 0x3F);
        if (u8)  atomicOr(&s_flags[0], 1);
        if (f32) atomicOr(&s_flags[1], 1);
    }

    // ---- stage dist tile (32 targets x 256 sources), coalesced ----
    {
        const float4* dsrc = (const float4*)(
            dist + (((size_t)(b * NLG + l)) * TT + tb * 32) * SS);
        #pragma unroll
        for (int i = 0; i < 8; i++) {
            int g = tid + i * 256;
            float4 v = dsrc[g];
            int flat = g * 4;
            int t = flat >> 8;
            int s = flat & 255;
            *(float4*)&sd[t * ROWST + offmap(s)] = v;
        }
    }
    __syncthreads();
    const int mkind = s_flags[0] ? 0 : (s_flags[1] ? 2 : 1);

    // ---- stage mask -> nibble table mnib[s] (tid = s), bit nv = masked ----
    {
        const size_t moff = ((size_t)((b * NTT + nt) * NLG + l)) * SS * NVV;
        int nib;
        if (mkind == 0) {
            const uchar4* msrc = (const uchar4*)((const unsigned char*)mask_raw + moff);
            uchar4 m = msrc[tid];
            nib = (m.x ? 1 : 0) | (m.y ? 2 : 0) | (m.z ? 4 : 0) | (m.w ? 8 : 0);
        } else if (mkind == 1) {
            const int4* msrc = (const int4*)((const int*)mask_raw + moff);
            int4 m = msrc[tid];
            nib = (m.x ? 1 : 0) | (m.y ? 2 : 0) | (m.z ? 4 : 0) | (m.w ? 8 : 0);
        } else {
            const float4* msrc = (const float4*)((const float*)mask_raw + moff);
            float4 m = msrc[tid];
            nib = (m.x != 0.0f ? 1 : 0) | (m.y != 0.0f ? 2 : 0) |
                  (m.z != 0.0f ? 4 : 0) | (m.w != 0.0f ? 8 : 0);
        }
        mnib[tid] = (unsigned char)nib;
    }
    __syncthreads();

    // ============ Phase A: threshold + compaction, one lane per (t,chunk) ==
    // lane owns t = tid>>3, chunk c = tid&7; chunk covers s = c + 8j.
    const int at = tid >> 3;
    const int ac = tid & 7;
    const float* dbt = &sd[at * ROWST];

    // chunk min with 4-way ILP tree (independent partials)
    float p0 = BIGV, p1 = BIGV, p2 = BIGV, p3 = BIGV;
    #pragma unroll
    for (int j = 0; j < 16; j += 4) {          // s < 128
        p0 = fminf(p0, dbt[ac + 8 * (j + 0)]);
        p1 = fminf(p1, dbt[ac + 8 * (j + 1)]);
        p2 = fminf(p2, dbt[ac + 8 * (j + 2)]);
        p3 = fminf(p3, dbt[ac + 8 * (j + 3)]);
    }
    #pragma unroll
    for (int j = 16; j < 32; j += 4) {         // s >= 128 (+4 pad)
        p0 = fminf(p0, dbt[ac + 8 * (j + 0) + 4]);
        p1 = fminf(p1, dbt[ac + 8 * (j + 1) + 4]);
        p2 = fminf(p2, dbt[ac + 8 * (j + 2) + 4]);
        p3 = fminf(p3, dbt[ac + 8 * (j + 3) + 4]);
    }
    float tau = fminf(fminf(p0, p1), fminf(p2, p3));
    tau = fmaxf(tau, __shfl_xor_sync(0xffffffffu, tau, 1));
    tau = fmaxf(tau, __shfl_xor_sync(0xffffffffu, tau, 2));
    tau = fmaxf(tau, __shfl_xor_sync(0xffffffffu, tau, 4));
    // >= 8 candidates of row t are <= tau.

    {   // compaction: re-read (SMEM-hot), write (value, s|nib) survivors
        float*          mypv = &pv  [at * TPST + ac * CAP];
        unsigned short* myps = &pssh[at * TPST + ac * CAP];
        int cnt = 0;
        #pragma unroll
        for (int j = 0; j < 32; j++) {
            int s = ac + 8 * j;
            float v = dbt[s + ((j >> 4) << 2)];   // +4 pad for j>=16
            if (v <= tau) {
                if (cnt < CAP) {
                    mypv[cnt] = v;
                    myps[cnt] = (unsigned short)(s | (mnib[s] << 8));
                }
                cnt++;
            }
        }
        cnts[at * 8 + ac] = (unsigned char)cnt;
    }
    __syncthreads();

    // ============ Phase B: exact top-3 over the pool (independent loads) ===
    const int nv = tid & 3;
    const int ph = (tid >> 2) & 1;
    const int t  = tid >> 3;                  // == at, tau is for this t

    float a0 = BIGV, a1 = BIGV, a2 = BIGV;
    int   ai0 = BIGI, ai1 = BIGI, ai2 = BIGI;
    int ovf = 0;

    const float*          tpv = &pv  [t * TPST];
    const unsigned short* tps = &pssh[t * TPST];
    #pragma unroll
    for (int c = 0; c < 8; c++) {
        int n = cnts[t * 8 + c];
        if (n > CAP) { ovf = 1; n = CAP; }
        const int base = c * CAP;
        for (int i = ph; i < n; i += 2) {
            float v          = tpv[base + i];
            unsigned short w = tps[base + i];
            int s = w & 255;
            if (!((w >> (8 + nv)) & 1))
                top3_insert_vi(v, s, a0, a1, a2, ai0, ai1, ai2);
        }
    }

    // merge the two ph lanes (partner = lane ^ 4) — shfls unconditional
    {
        float ov0 = __shfl_xor_sync(0xffffffffu, a0, 4);
        float ov1 = __shfl_xor_sync(0xffffffffu, a1, 4);
        float ov2 = __shfl_xor_sync(0xffffffffu, a2, 4);
        int   oi0 = __shfl_xor_sync(0xffffffffu, ai0, 4);
        int   oi1 = __shfl_xor_sync(0xffffffffu, ai1, 4);
        int   oi2 = __shfl_xor_sync(0xffffffffu, ai2, 4);
        top3_insert_vi(ov0, oi0, a0, a1, a2, ai0, ai1, ai2);
        top3_insert_vi(ov1, oi1, a0, a1, a2, ai0, ai1, ai2);
        top3_insert_vi(ov2, oi2, a0, a1, a2, ai0, ai1, ai2);
    }
    int ovf_other = __shfl_xor_sync(0xffffffffu, ovf, 4);   // never short-circuit a shfl
    ovf |= ovf_other;

    // exactness: excluded unmasked sources have dist > tau (>= lex above a2);
    // masked ones behave as +1e6 > tau. a2 <= tau and no overflow => exact.
    bool flag = (ovf != 0) || (a2 > tau);
    if (__any_sync(0xffffffffu, flag)) {
        const float* dt = &sd[t * ROWST];
        float f0 = BIGV, f1 = BIGV, f2 = BIGV;
        int   g0 = BIGI, g1 = BIGI, g2 = BIGI;
        for (int k = 0; k < 128; k++) {
            int s = (k << 1) | ph;
            float pen = ((mnib[s] >> nv) & 1) ? MASKVAL : 0.0f;
            float v = dt[offmap(s)] + pen;
            top3_insert_vi(v, s, f0, f1, f2, g0, g1, g2);
        }
        float ov0 = __shfl_xor_sync(0xffffffffu, f0, 4);
        float ov1 = __shfl_xor_sync(0xffffffffu, f1, 4);
        float ov2 = __shfl_xor_sync(0xffffffffu, f2, 4);
        int   oi0 = __shfl_xor_sync(0xffffffffu, g0, 4);
        int   oi1 = __shfl_xor_sync(0xffffffffu, g1, 4);
        int   oi2 = __shfl_xor_sync(0xffffffffu, g2, 4);
        top3_insert_vi(ov0, oi0, f0, f1, f2, g0, g1, g2);
        top3_insert_vi(ov1, oi1, f0, f1, f2, g0, g1, g2);
        top3_insert_vi(ov2, oi2, f0, f1, f2, g0, g1, g2);
        if (flag) {
            a0 = f0; a1 = f1; a2 = f2;
            ai0 = g0; ai1 = g1; ai2 = g2;
        }
    }

    // ---- weights ----
    float q0 = fmaxf(a0, CUTOFF);
    float q1 = fmaxf(a1, CUTOFF);
    float q2 = fmaxf(a2, CUTOFF);
    float w0 = 1.0f / (q0 * q0);
    float w1 = 1.0f / (q1 * q1);
    float w2 = 1.0f / (q2 * q2);
    float inv = 1.0f / (w0 + w1 + w2);
    w0 *= inv; w1 *= inv; w2 *= inv;

    // ---- gather + blend: each ph lane writes 2 of the 4 float4s ----
    const int tg = t + tb * 32;               // global target 0..63
    const float* xb = x + ((size_t)((b * NTT + nt) * NLG + l)) * SS * NVV * FF;
    const float4* xp0 = (const float4*)(xb + ((size_t)ai0 * NVV + nv) * FF);
    const float4* xp1 = (const float4*)(xb + ((size_t)ai1 * NVV + nv) * FF);
    const float4* xp2 = (const float4*)(xb + ((size_t)ai2 * NVV + nv) * FF);

    const size_t row = (size_t)((b * NTT + nt) * (NLG * TT)) + (size_t)l * TT + tg;
    float4* op = (float4*)(out + (row * NVV + nv) * FF);

    const int j0 = ph * 2;
    #pragma unroll
    for (int j = j0; j < j0 + 2; j++) {
        float4 va = xp0[j], vb = xp1[j], vc = xp2[j];
        float4 rr;
        rr.x = w0 * va.x + w1 * vb.x + w2 * vc.x;
        rr.y = w0 * va.y + w1 * vb.y + w2 * vc.y;
        rr.z = w0 * va.z + w1 * vb.z + w2 * vc.z;
        rr.w = w0 * va.w + w1 * vb.w + w2 * vc.w;
        op[j] = rr;
    }

    // ---- dist_vals output: split between the two ph lanes ----
    const size_t XSZ = (size_t)NB * NTT * NLG * TT * NVV * FF;  // 4,194,304
    size_t dbaseo = XSZ + (row * KNN) * NVV + nv;
    if (ph == 0) {
        out[dbaseo]       = q0;
        out[dbaseo + NVV] = q1;
    } else {
        out[dbaseo + 2 * NVV] = q2;
    }
}

extern "C" void kernel_launch(void* const* d_in, const int* in_sizes, int n_in,
                              void* d_out, int out_size) {
    const float* x    = (const float*)d_in[0];
    const void*  mask = (const void*)d_in[1];
    const float* dist = (const float*)d_in[2];
    float*       out  = (float*)d_out;

    cudaFuncSetAttribute(interp_kernel,
                         cudaFuncAttributeMaxDynamicSharedMemorySize, SMEM_BYTES);
    interp_kernel<<<NB * NTT * NLG * 2, 256, SMEM_BYTES>>>(x, mask, dist, out);
}

// round 11
// speedup vs baseline: 1.2917x; 1.2917x over previous
#include <cuda_runtime.h>
#include <cstdint>

#define NB    2
#define NTT   2
#define NLG   256
#define TT    64
#define SS    256
#define NVV   4
#define FF    16
#define KNN   3
#define CUTOFF   1e-3f
#define MASKVAL  1e6f

#define ROWST 264          // dist tile row stride (floats), pad 4 at s=128
#define CAP   16           // pool capacity per (t, chunk)
#define PSS   144          // ushort pool stride per t (8*CAP=128 + 16 pad -> 8-bank shift)

#define BIGV 3.4e38f
#define BIGI 0x3fffffff

__device__ __forceinline__ bool lessvi(float v, int i, float w, int j) {
    return (v < w) || (v == w && i < j);
}

// exact lexicographic (value, index) top-3 insert
__device__ __forceinline__ void top3_insert_vi(float v, int s,
                                               float& d0, float& d1, float& d2,
                                               int& i0, int& i1, int& i2) {
    if (lessvi(v, s, d2, i2)) {
        if (lessvi(v, s, d1, i1)) {
            d2 = d1; i2 = i1;
            if (lessvi(v, s, d0, i0)) { d1 = d0; i1 = i0; d0 = v; i0 = s; }
            else                      { d1 = v;  i1 = s; }
        } else {
            d2 = v; i2 = s;
        }
    }
}

__device__ __forceinline__ int offmap(int s) {  // s -> padded tile offset
    return s + ((s >> 7) << 2);                 // s<128: s ; s>=128: s+4
}

__global__ __launch_bounds__(256, 5) void interp_kernel(
    const float* __restrict__ x,            // (B,NT, NL*S, NV, F)
    const void*  __restrict__ mask_raw,     // (B,NT, NL*S, NV) — dtype detected
    const float* __restrict__ dist,         // (B, NL, T, S)
    float* __restrict__ out)
{
    __shared__ float          sdist [32 * ROWST];   // 33.8 KB
    __shared__ unsigned short poolsb[32 * PSS];     // 9 KB   s | nibble<<8
    __shared__ unsigned char  mnib  [SS];           // 256 B mask nibbles per s
    __shared__ unsigned char  cnts  [32 * 8];       // raw counts
    __shared__ int s_flags[2];

    const int bid   = blockIdx.x;
    const int tb    = bid & 1;               // half of the 64 targets
    const int group = bid >> 1;
    const int l     = group & 255;
    const int nt    = (group >> 8) & 1;
    const int b     = group >> 9;
    const int tid   = threadIdx.x;

    if (tid == 0) { s_flags[0] = 0; s_flags[1] = 0; }
    __syncthreads();

    // ---- mask dtype detection from first 1024 bytes ----
    {
        const uchar4* mb = (const uchar4*)mask_raw;
        uchar4 q = mb[tid];
        int u8  = (q.y == 1) | (q.z == 1) | (q.w == 1);
        int f32 = (q.x == 0x3F) | (q.y == 0x3F) | (q.z == 0x3F) | (q.w == 0x3F);
        if (u8)  atomicOr(&s_flags[0], 1);
        if (f32) atomicOr(&s_flags[1], 1);
    }

    // ---- stage dist tile (32 targets x 256 sources), coalesced ----
    {
        const float4* dsrc = (const float4*)(
            dist + (((size_t)(b * NLG + l)) * TT + tb * 32) * SS);
        #pragma unroll
        for (int i = 0; i < 8; i++) {
            int g = tid + i * 256;
            float4 v = dsrc[g];
            int flat = g * 4;
            int t = flat >> 8;
            int s = flat & 255;
            *(float4*)&sdist[t * ROWST + offmap(s)] = v;
        }
    }
    __syncthreads();
    const int mkind = s_flags[0] ? 0 : (s_flags[1] ? 2 : 1);

    // ---- stage mask -> nibble table mnib[s] (tid = s), bit nv = masked ----
    {
        const size_t moff = ((size_t)((b * NTT + nt) * NLG + l)) * SS * NVV;
        int nib;
        if (mkind == 0) {
            const uchar4* msrc = (const uchar4*)((const unsigned char*)mask_raw + moff);
            uchar4 m = msrc[tid];
            nib = (m.x ? 1 : 0) | (m.y ? 2 : 0) | (m.z ? 4 : 0) | (m.w ? 8 : 0);
        } else if (mkind == 1) {
            const int4* msrc = (const int4*)((const int*)mask_raw + moff);
            int4 m = msrc[tid];
            nib = (m.x ? 1 : 0) | (m.y ? 2 : 0) | (m.z ? 4 : 0) | (m.w ? 8 : 0);
        } else {
            const float4* msrc = (const float4*)((const float*)mask_raw + moff);
            float4 m = msrc[tid];
            nib = (m.x != 0.0f ? 1 : 0) | (m.y != 0.0f ? 2 : 0) |
                  (m.z != 0.0f ? 4 : 0) | (m.w != 0.0f ? 8 : 0);
        }
        mnib[tid] = (unsigned char)nib;
    }
    __syncthreads();

    // ============ Phase A: threshold + compaction, one lane per (t,chunk) ==
    // lane owns t = tid>>3, chunk c = tid&7; chunk covers s = c + 8j (interleaved)
    const int at = tid >> 3;
    const int ac = tid & 7;
    const float* dbt = &sdist[at * ROWST];

    // chunk min with 4-way ILP tree (independent partials, same loads as R7)
    float q0 = BIGV, q1 = BIGV, q2 = BIGV, q3 = BIGV;
    #pragma unroll
    for (int j = 0; j < 16; j += 4) {          // s < 128
        q0 = fminf(q0, dbt[ac + 8 * (j + 0)]);
        q1 = fminf(q1, dbt[ac + 8 * (j + 1)]);
        q2 = fminf(q2, dbt[ac + 8 * (j + 2)]);
        q3 = fminf(q3, dbt[ac + 8 * (j + 3)]);
    }
    #pragma unroll
    for (int j = 16; j < 32; j += 4) {         // s >= 128 (+4 pad)
        q0 = fminf(q0, dbt[ac + 8 * (j + 0) + 4]);
        q1 = fminf(q1, dbt[ac + 8 * (j + 1) + 4]);
        q2 = fminf(q2, dbt[ac + 8 * (j + 2) + 4]);
        q3 = fminf(q3, dbt[ac + 8 * (j + 3) + 4]);
    }
    float tau = fminf(fminf(q0, q1), fminf(q2, q3));
    tau = fmaxf(tau, __shfl_xor_sync(0xffffffffu, tau, 1));
    tau = fmaxf(tau, __shfl_xor_sync(0xffffffffu, tau, 2));
    tau = fmaxf(tau, __shfl_xor_sync(0xffffffffu, tau, 4));
    // >= 8 candidates of row t are <= tau.

    {   // compaction: survivors' (s | nib<<8) into the ushort pool
        unsigned short* myps = &poolsb[at * PSS + ac * CAP];
        int cnt = 0;
        #pragma unroll
        for (int j = 0; j < 16; j++) {
            int s = ac + 8 * j;
            float v = dbt[s];
            if (v <= tau) {
                if (cnt < CAP) myps[cnt] = (unsigned short)(s | (mnib[s] << 8));
                cnt++;
            }
        }
        #pragma unroll
        for (int j = 16; j < 32; j++) {
            int s = ac + 8 * j;
            float v = dbt[s + 4];
            if (v <= tau) {
                if (cnt < CAP) myps[cnt] = (unsigned short)(s | (mnib[s] << 8));
                cnt++;
            }
        }
        cnts[at * 8 + ac] = (unsigned char)cnt;
    }
    __syncthreads();

    // ============ Phase B: exact top-3 over the pool ============
    const int nv = tid & 3;
    const int ph = (tid >> 2) & 1;
    const int t  = tid >> 3;                 // == at, tau valid for this t
    const float* dt = &sdist[t * ROWST];

    float a0 = BIGV, a1 = BIGV, a2 = BIGV;
    int   ai0 = BIGI, ai1 = BIGI, ai2 = BIGI;
    int ovf = 0;

    const unsigned short* tps = &poolsb[t * PSS];
    #pragma unroll
    for (int c = 0; c < 8; c++) {
        int n = cnts[t * 8 + c];
        if (n > CAP) { ovf = 1; n = CAP; }
        const int base = c * CAP;
        for (int i = ph; i < n; i += 2) {
            unsigned short w = tps[base + i];
            int s = w & 255;
            if (!((w >> (8 + nv)) & 1)) {
                float v = dt[offmap(s)];
                top3_insert_vi(v, s, a0, a1, a2, ai0, ai1, ai2);
            }
        }
    }

    // merge the two ph lanes (partner = lane ^ 4) — shfls unconditional
    {
        float ov0 = __shfl_xor_sync(0xffffffffu, a0, 4);
        float ov1 = __shfl_xor_sync(0xffffffffu, a1, 4);
        float ov2 = __shfl_xor_sync(0xffffffffu, a2, 4);
        int   oi0 = __shfl_xor_sync(0xffffffffu, ai0, 4);
        int   oi1 = __shfl_xor_sync(0xffffffffu, ai1, 4);
        int   oi2 = __shfl_xor_sync(0xffffffffu, ai2, 4);
        top3_insert_vi(ov0, oi0, a0, a1, a2, ai0, ai1, ai2);
        top3_insert_vi(ov1, oi1, a0, a1, a2, ai0, ai1, ai2);
        top3_insert_vi(ov2, oi2, a0, a1, a2, ai0, ai1, ai2);
    }
    int ovf_other = __shfl_xor_sync(0xffffffffu, ovf, 4);   // never short-circuit a shfl
    ovf |= ovf_other;

    // exactness: excluded unmasked sources have dist > tau; masked pooled
    // entries are skipped (== +1e6 behavior). a2 <= tau and no overflow => exact.
    bool flag = (ovf != 0) || (a2 > tau);
    if (__any_sync(0xffffffffu, flag)) {
        float f0 = BIGV, f1 = BIGV, f2 = BIGV;
        int   g0 = BIGI, g1 = BIGI, g2 = BIGI;
        for (int k = 0; k < 128; k++) {
            int s = (k << 1) | ph;
            float pen = ((mnib[s] >> nv) & 1) ? MASKVAL : 0.0f;
            float v = dt[offmap(s)] + pen;
            top3_insert_vi(v, s, f0, f1, f2, g0, g1, g2);
        }
        float ov0 = __shfl_xor_sync(0xffffffffu, f0, 4);
        float ov1 = __shfl_xor_sync(0xffffffffu, f1, 4);
        float ov2 = __shfl_xor_sync(0xffffffffu, f2, 4);
        int   oi0 = __shfl_xor_sync(0xffffffffu, g0, 4);
        int   oi1 = __shfl_xor_sync(0xffffffffu, g1, 4);
        int   oi2 = __shfl_xor_sync(0xffffffffu, g2, 4);
        top3_insert_vi(ov0, oi0, f0, f1, f2, g0, g1, g2);
        top3_insert_vi(ov1, oi1, f0, f1, f2, g0, g1, g2);
        top3_insert_vi(ov2, oi2, f0, f1, f2, g0, g1, g2);
        if (flag) {
            a0 = f0; a1 = f1; a2 = f2;
            ai0 = g0; ai1 = g1; ai2 = g2;
        }
    }

    // ---- weights ----
    float c0 = fmaxf(a0, CUTOFF);
    float c1 = fmaxf(a1, CUTOFF);
    float c2 = fmaxf(a2, CUTOFF);
    float w0 = 1.0f / (c0 * c0);
    float w1 = 1.0f / (c1 * c1);
    float w2 = 1.0f / (c2 * c2);
    float inv = 1.0f / (w0 + w1 + w2);
    w0 *= inv; w1 *= inv; w2 *= inv;

    // ---- gather + blend: each ph lane writes 2 of the 4 float4s ----
    const int tg = t + tb * 32;               // global target 0..63
    const float* xb = x + ((size_t)((b * NTT + nt) * NLG + l)) * SS * NVV * FF;
    const float4* xp0 = (const float4*)(xb + ((size_t)ai0 * NVV + nv) * FF);
    const float4* xp1 = (const float4*)(xb + ((size_t)ai1 * NVV + nv) * FF);
    const float4* xp2 = (const float4*)(xb + ((size_t)ai2 * NVV + nv) * FF);

    const size_t row = (size_t)((b * NTT + nt) * (NLG * TT)) + (size_t)l * TT + tg;
    float4* op = (float4*)(out + (row * NVV + nv) * FF);

    const int j0 = ph * 2;
    #pragma unroll
    for (int j = j0; j < j0 + 2; j++) {
        float4 va = xp0[j], vb = xp1[j], vc = xp2[j];
        float4 rr;
        rr.x = w0 * va.x + w1 * vb.x + w2 * vc.x;
        rr.y = w0 * va.y + w1 * vb.y + w2 * vc.y;
        rr.z = w0 * va.z + w1 * vb.z + w2 * vc.z;
        rr.w = w0 * va.w + w1 * vb.w + w2 * vc.w;
        op[j] = rr;
    }

    // ---- dist_vals output: split between the two ph lanes ----
    const size_t XSZ = (size_t)NB * NTT * NLG * TT * NVV * FF;  // 4,194,304
    size_t dbaseo = XSZ + (row * KNN) * NVV + nv;
    if (ph == 0) {
        out[dbaseo]       = c0;
        out[dbaseo + NVV] = c1;
    } else {
        out[dbaseo + 2 * NVV] = c2;
    }
}

extern "C" void kernel_launch(void* const* d_in, const int* in_sizes, int n_in,
                              void* d_out, int out_size) {
    const float* x    = (const float*)d_in[0];
    const void*  mask = (const void*)d_in[1];
    const float* dist = (const float*)d_in[2];
    float*       out  = (float*)d_out;

    interp_kernel<<<NB * NTT * NLG * 2, 256>>>(x, mask, dist, out);
}

// round 12
// speedup vs baseline: 1.3598x; 1.0528x over previous
#include <cuda_runtime.h>
#include <cstdint>

#define NB    2
#define NTT   2
#define NLG   256
#define TT    64
#define SS    256
#define NVV   4
#define FF    16
#define KNN   3
#define CUTOFF   1e-3f
#define MASKVAL  1e6f

#define NT_CTA 16          // targets per CTA
#define NTHR   128         // threads per CTA
#define ROWST  264         // dist tile row stride (floats), pad 4 at s=128
#define CAP    16          // pool capacity per (t, chunk)
#define PSTR   136         // byte pool stride per t (8*CAP + 8 -> de-conflicted)

#define BIGV 3.4e38f
#define BIGI 0x3fffffff

__device__ __forceinline__ bool lessvi(float v, int i, float w, int j) {
    return (v < w) || (v == w && i < j);
}

// exact lexicographic (value, index) top-3 insert
__device__ __forceinline__ void top3_insert_vi(float v, int s,
                                               float& d0, float& d1, float& d2,
                                               int& i0, int& i1, int& i2) {
    if (lessvi(v, s, d2, i2)) {
        if (lessvi(v, s, d1, i1)) {
            d2 = d1; i2 = i1;
            if (lessvi(v, s, d0, i0)) { d1 = d0; i1 = i0; d0 = v; i0 = s; }
            else                      { d1 = v;  i1 = s; }
        } else {
            d2 = v; i2 = s;
        }
    }
}

__device__ __forceinline__ int offmap(int s) {  // s -> padded tile offset
    return s + ((s >> 7) << 2);                 // s<128: s ; s>=128: s+4
}

__global__ __launch_bounds__(NTHR, 10) void interp_kernel(
    const float* __restrict__ x,            // (B,NT, NL*S, NV, F)
    const void*  __restrict__ mask_raw,     // (B,NT, NL*S, NV) — dtype detected
    const float* __restrict__ dist,         // (B, NL, T, S)
    float* __restrict__ out)
{
    __shared__ float         sdist[NT_CTA * ROWST];    // 16.5 KB
    __shared__ float         spen [NVV * ROWST];       // 4.2 KB penalty table
    __shared__ unsigned char pool [NT_CTA * PSTR];     // 2.1 KB survivor indices
    __shared__ unsigned char cnts [NT_CTA * 8];        // raw counts
    __shared__ int s_flags[2];

    const int bid   = blockIdx.x;
    const int tb    = bid & 3;               // which 16-target slice of 64
    const int group = bid >> 2;
    const int l     = group & 255;
    const int nt    = (group >> 8) & 1;
    const int b     = group >> 9;
    const int tid   = threadIdx.x;

    if (tid == 0) { s_flags[0] = 0; s_flags[1] = 0; }
    __syncthreads();

    // ---- mask dtype detection from first 1024 bytes ----
    {
        const uchar4* mb = (const uchar4*)mask_raw;
        int u8 = 0, f32 = 0;
        #pragma unroll
        for (int r = 0; r < 2; r++) {
            uchar4 q = mb[tid + r * NTHR];
            u8  |= (q.y == 1) | (q.z == 1) | (q.w == 1);
            f32 |= (q.x == 0x3F) | (q.y == 0x3F) | (q.z == 0x3F) | (q.w == 0x3F);
        }
        if (u8)  atomicOr(&s_flags[0], 1);
        if (f32) atomicOr(&s_flags[1], 1);
    }

    // ---- stage dist tile (16 targets x 256 sources), coalesced ----
    {
        const float4* dsrc = (const float4*)(
            dist + (((size_t)(b * NLG + l)) * TT + tb * NT_CTA) * SS);
        #pragma unroll
        for (int i = 0; i < 8; i++) {
            int g = tid + i * NTHR;
            float4 v = dsrc[g];
            int flat = g * 4;
            int t = flat >> 8;                // 0..15
            int s = flat & 255;
            *(float4*)&sdist[t * ROWST + offmap(s)] = v;
        }
    }
    __syncthreads();
    const int mkind = s_flags[0] ? 0 : (s_flags[1] ? 2 : 1);

    // ---- stage mask -> penalty table spen[nv][offmap(s)] ----
    {
        const size_t moff = ((size_t)((b * NTT + nt) * NLG + l)) * SS * NVV;
        #pragma unroll
        for (int r = 0; r < 2; r++) {
            int s0 = tid + r * NTHR;          // source index 0..255
            float* pb = &spen[offmap(s0)];
            if (mkind == 0) {
                const uchar4* msrc = (const uchar4*)((const unsigned char*)mask_raw + moff);
                uchar4 m = msrc[s0];
                pb[0 * ROWST] = m.x ? MASKVAL : 0.0f;
                pb[1 * ROWST] = m.y ? MASKVAL : 0.0f;
                pb[2 * ROWST] = m.z ? MASKVAL : 0.0f;
                pb[3 * ROWST] = m.w ? MASKVAL : 0.0f;
            } else if (mkind == 1) {
                const int4* msrc = (const int4*)((const int*)mask_raw + moff);
                int4 m = msrc[s0];
                pb[0 * ROWST] = m.x ? MASKVAL : 0.0f;
                pb[1 * ROWST] = m.y ? MASKVAL : 0.0f;
                pb[2 * ROWST] = m.z ? MASKVAL : 0.0f;
                pb[3 * ROWST] = m.w ? MASKVAL : 0.0f;
            } else {
                const float4* msrc = (const float4*)((const float*)mask_raw + moff);
                float4 m = msrc[s0];
                pb[0 * ROWST] = m.x * MASKVAL;
                pb[1 * ROWST] = m.y * MASKVAL;
                pb[2 * ROWST] = m.z * MASKVAL;
                pb[3 * ROWST] = m.w * MASKVAL;
            }
        }
    }
    __syncthreads();

    // ============ Phase A: threshold + compaction, one lane per (t,chunk) ==
    // lane owns t = tid>>3 (0..15), chunk c = tid&7; chunk covers s = c + 8j.
    const int at = tid >> 3;
    const int ac = tid & 7;
    const float* dbt = &sdist[at * ROWST];

    // chunk min with 4-way ILP tree
    float q0 = BIGV, q1 = BIGV, q2 = BIGV, q3 = BIGV;
    #pragma unroll
    for (int j = 0; j < 16; j += 4) {          // s < 128
        q0 = fminf(q0, dbt[ac + 8 * (j + 0)]);
        q1 = fminf(q1, dbt[ac + 8 * (j + 1)]);
        q2 = fminf(q2, dbt[ac + 8 * (j + 2)]);
        q3 = fminf(q3, dbt[ac + 8 * (j + 3)]);
    }
    #pragma unroll
    for (int j = 16; j < 32; j += 4) {         // s >= 128 (+4 pad)
        q0 = fminf(q0, dbt[ac + 8 * (j + 0) + 4]);
        q1 = fminf(q1, dbt[ac + 8 * (j + 1) + 4]);
        q2 = fminf(q2, dbt[ac + 8 * (j + 2) + 4]);
        q3 = fminf(q3, dbt[ac + 8 * (j + 3) + 4]);
    }
    float tau = fminf(fminf(q0, q1), fminf(q2, q3));
    tau = fmaxf(tau, __shfl_xor_sync(0xffffffffu, tau, 1));
    tau = fmaxf(tau, __shfl_xor_sync(0xffffffffu, tau, 2));
    tau = fmaxf(tau, __shfl_xor_sync(0xffffffffu, tau, 4));
    // >= 8 candidates of row t are <= tau.

    {   // compaction of survivor indices into the byte pool
        unsigned char* mypool = &pool[at * PSTR + ac * CAP];
        int cnt = 0;
        #pragma unroll
        for (int j = 0; j < 16; j++) {
            int s = ac + 8 * j;
            if (dbt[s] <= tau) { if (cnt < CAP) mypool[cnt] = (unsigned char)s; cnt++; }
        }
        #pragma unroll
        for (int j = 16; j < 32; j++) {
            int s = ac + 8 * j;
            if (dbt[s + 4] <= tau) { if (cnt < CAP) mypool[cnt] = (unsigned char)s; cnt++; }
        }
        cnts[at * 8 + ac] = (unsigned char)cnt;
    }
    __syncthreads();

    // ============ Phase B: exact top-3 over the pool ============
    const int nv = tid & 3;
    const int ph = (tid >> 2) & 1;
    const int t  = tid >> 3;                  // == at, tau valid for this t
    const float* dt = &sdist[t * ROWST];
    const float* pn = &spen[nv * ROWST];

    float a0 = BIGV, a1 = BIGV, a2 = BIGV;
    int   ai0 = BIGI, ai1 = BIGI, ai2 = BIGI;
    int ovf = 0;

    #pragma unroll
    for (int c = 0; c < 8; c++) {
        int n = cnts[t * 8 + c];
        if (n > CAP) { ovf = 1; n = CAP; }
        const unsigned char* pp = &pool[t * PSTR + c * CAP];
        for (int i = ph; i < n; i += 2) {
            int s = pp[i];
            int off = offmap(s);
            float v = dt[off] + pn[off];      // masked -> +1e6, branch-free
            top3_insert_vi(v, s, a0, a1, a2, ai0, ai1, ai2);
        }
    }

    // merge the two ph lanes (partner = lane ^ 4) — shfls unconditional
    {
        float ov0 = __shfl_xor_sync(0xffffffffu, a0, 4);
        float ov1 = __shfl_xor_sync(0xffffffffu, a1, 4);
        float ov2 = __shfl_xor_sync(0xffffffffu, a2, 4);
        int   oi0 = __shfl_xor_sync(0xffffffffu, ai0, 4);
        int   oi1 = __shfl_xor_sync(0xffffffffu, ai1, 4);
        int   oi2 = __shfl_xor_sync(0xffffffffu, ai2, 4);
        top3_insert_vi(ov0, oi0, a0, a1, a2, ai0, ai1, ai2);
        top3_insert_vi(ov1, oi1, a0, a1, a2, ai0, ai1, ai2);
        top3_insert_vi(ov2, oi2, a0, a1, a2, ai0, ai1, ai2);
    }
    int ovf_other = __shfl_xor_sync(0xffffffffu, ovf, 4);   // never short-circuit a shfl
    ovf |= ovf_other;

    // exactness: excluded unmasked sources have dist > tau; masked pooled
    // entries carry +1e6 > tau. a2 <= tau and no overflow => exact.
    bool flag = (ovf != 0) || (a2 > tau);
    if (__any_sync(0xffffffffu, flag)) {
        float f0 = BIGV, f1 = BIGV, f2 = BIGV;
        int   g0 = BIGI, g1 = BIGI, g2 = BIGI;
        for (int k = 0; k < 128; k++) {
            int s = (k << 1) | ph;
            int off = offmap(s);
            float v = dt[off] + pn[off];
            top3_insert_vi(v, s, f0, f1, f2, g0, g1, g2);
        }
        float ov0 = __shfl_xor_sync(0xffffffffu, f0, 4);
        float ov1 = __shfl_xor_sync(0xffffffffu, f1, 4);
        float ov2 = __shfl_xor_sync(0xffffffffu, f2, 4);
        int   oi0 = __shfl_xor_sync(0xffffffffu, g0, 4);
        int   oi1 = __shfl_xor_sync(0xffffffffu, g1, 4);
        int   oi2 = __shfl_xor_sync(0xffffffffu, g2, 4);
        top3_insert_vi(ov0, oi0, f0, f1, f2, g0, g1, g2);
        top3_insert_vi(ov1, oi1, f0, f1, f2, g0, g1, g2);
        top3_insert_vi(ov2, oi2, f0, f1, f2, g0, g1, g2);
        if (flag) {
            a0 = f0; a1 = f1; a2 = f2;
            ai0 = g0; ai1 = g1; ai2 = g2;
        }
    }

    // ---- weights ----
    float c0 = fmaxf(a0, CUTOFF);
    float c1 = fmaxf(a1, CUTOFF);
    float c2 = fmaxf(a2, CUTOFF);
    float w0 = 1.0f / (c0 * c0);
    float w1 = 1.0f / (c1 * c1);
    float w2 = 1.0f / (c2 * c2);
    float inv = 1.0f / (w0 + w1 + w2);
    w0 *= inv; w1 *= inv; w2 *= inv;

    // ---- gather + blend: each ph lane writes 2 of the 4 float4s ----
    const int tg = t + tb * NT_CTA;            // global target 0..63
    const float* xb = x + ((size_t)((b * NTT + nt) * NLG + l)) * SS * NVV * FF;
    const float4* xp0 = (const float4*)(xb + ((size_t)ai0 * NVV + nv) * FF);
    const float4* xp1 = (const float4*)(xb + ((size_t)ai1 * NVV + nv) * FF);
    const float4* xp2 = (const float4*)(xb + ((size_t)ai2 * NVV + nv) * FF);

    const size_t row = (size_t)((b * NTT + nt) * (NLG * TT)) + (size_t)l * TT + tg;
    float4* op = (float4*)(out + (row * NVV + nv) * FF);

    const int j0 = ph * 2;
    #pragma unroll
    for (int j = j0; j < j0 + 2; j++) {
        float4 va = xp0[j], vb = xp1[j], vc = xp2[j];
        float4 rr;
        rr.x = w0 * va.x + w1 * vb.x + w2 * vc.x;
        rr.y = w0 * va.y + w1 * vb.y + w2 * vc.y;
        rr.z = w0 * va.z + w1 * vb.z + w2 * vc.z;
        rr.w = w0 * va.w + w1 * vb.w + w2 * vc.w;
        op[j] = rr;
    }

    // ---- dist_vals output: split between the two ph lanes ----
    const size_t XSZ = (size_t)NB * NTT * NLG * TT * NVV * FF;  // 4,194,304
    size_t dbaseo = XSZ + (row * KNN) * NVV + nv;
    if (ph == 0) {
        out[dbaseo]       = c0;
        out[dbaseo + NVV] = c1;
    } else {
        out[dbaseo + 2 * NVV] = c2;
    }
}

extern "C" void kernel_launch(void* const* d_in, const int* in_sizes, int n_in,
                              void* d_out, int out_size) {
    const float* x    = (const float*)d_in[0];
    const void*  mask = (const void*)d_in[1];
    const float* dist = (const float*)d_in[2];
    float*       out  = (float*)d_out;

    interp_kernel<<<NB * NTT * NLG * 4, NTHR>>>(x, mask, dist, out);
}